// round 15
// baseline (speedup 1.0000x reference)
#include <cuda_runtime.h>
#include <cuda_bf16.h>
#include <math.h>

// Problem constants (from reference)
#define NUM_POS_FEATS 64          // F
#define N_AXES 3
#define MAX_COORD 128             // SPATIAL dims are all 128
#define TABLE_ELEMS (N_AXES * MAX_COORD * NUM_POS_FEATS)   // 24576 floats = 96 KB

// Lookup table: table[(c*128 + q)*64 + f]
//   f even: sin(q_norm_c / dim_t[f]),  f odd: cos(q_norm_c / dim_t[f])
__device__ float g_table[TABLE_ELEMS];

// All-fp32 table build: rel-err budget is 1e-3, fp32 sinf/cosf give ~1e-7.
__global__ void build_table_kernel(const int* __restrict__ sx,
                                   const int* __restrict__ sy,
                                   const int* __restrict__ sz) {
    int idx = blockIdx.x * blockDim.x + threadIdx.x;
    if (idx >= TABLE_ELEMS) return;
    int c   = idx / (MAX_COORD * NUM_POS_FEATS);
    int rem = idx - c * (MAX_COORD * NUM_POS_FEATS);
    int q   = rem / NUM_POS_FEATS;
    int f   = rem - q * NUM_POS_FEATS;

    int S = (c == 0) ? *sx : (c == 1) ? *sy : *sz;

    // vals = q/(S-1+eps) * 2*pi ; dim_t = 10000^(2*(f/2)/64) ; p = vals/dim_t
    float denom = (float)(S - 1) + 1.0e-06f;
    float val   = ((float)q / denom) * 6.2831853071795864769f;
    float ex    = (float)(f >> 1) * (13.287712379549449f / 32.0f);   // log2(10000)/32
    float dt    = exp2f(ex);
    float p     = val / dt;
    g_table[idx] = (f & 1) ? cosf(p) : sinf(p);
}

// Warp-stride unroll-8 in TWO WAVES of 4 (load4 -> store4 -> load4 -> store4):
// keeps the front-batched LDG schedule of the R13 two-phase kernel (MLP_p1=4
// per wave; wave-2 loads issue while wave-1 stores drain) while cutting live
// registers from 8xfloat4 to 4xfloat4, restoring 8 blocks/SM occupancy.
// Each warp owns 256 consecutive output float4s; lane l handles quads
// base+l+32*i: every STG is a fully-coalesced 512B warp write. __stcs
// because the 251.6MB output exceeds L2 (126MB). Exact grid: no predication.
__global__ void __launch_bounds__(256, 8) fill_kernel_exact(const int* __restrict__ coords,
                                                            float4* __restrict__ out) {
    const unsigned warp_id = (unsigned)(blockIdx.x * (blockDim.x >> 5) + (threadIdx.x >> 5));
    const unsigned lane    = threadIdx.x & 31u;
    const unsigned base    = warp_id * 256u + lane;

    const float4* tbl = reinterpret_cast<const float4*>(g_table);

#pragma unroll
    for (int w = 0; w < 2; w++) {
        float4 v[4];
#pragma unroll
        for (int i = 0; i < 4; i++) {
            unsigned g  = base + (unsigned)(w * 4 + i) * 32u;
            unsigned m  = g / 48u;           // point index
            unsigned r  = g - m * 48u;
            unsigned c  = r >> 4;            // axis 0..2
            unsigned fq = r & 15u;           // float4 within the 64-feature block

            int q = __ldg(&coords[m * 4u + 1u + c]);   // 0..127
            v[i] = tbl[(c * (unsigned)MAX_COORD + (unsigned)q) * 16u + fq];
        }
#pragma unroll
        for (int i = 0; i < 4; i++) {
            __stcs(&out[base + (unsigned)(w * 4 + i) * 32u], v[i]);
        }
    }
}

// Guarded fallback for shapes not divisible by 2048 quads.
__global__ void __launch_bounds__(256) fill_kernel_guarded(const int* __restrict__ coords,
                                                           float4* __restrict__ out,
                                                           unsigned total_quads) {
    const unsigned warp_id = (unsigned)(blockIdx.x * (blockDim.x >> 5) + (threadIdx.x >> 5));
    const unsigned lane    = threadIdx.x & 31u;
    const unsigned base    = warp_id * 256u + lane;

    const float4* tbl = reinterpret_cast<const float4*>(g_table);

#pragma unroll
    for (int i = 0; i < 8; i++) {
        unsigned g = base + (unsigned)i * 32u;
        if (g < total_quads) {
            unsigned m  = g / 48u;
            unsigned r  = g - m * 48u;
            unsigned c  = r >> 4;
            unsigned fq = r & 15u;
            int q = __ldg(&coords[m * 4u + 1u + c]);
            float4 v = tbl[(c * (unsigned)MAX_COORD + (unsigned)q) * 16u + fq];
            __stcs(&out[g], v);
        }
    }
}

extern "C" void kernel_launch(void* const* d_in, const int* in_sizes, int n_in,
                              void* d_out, int out_size) {
    const int* coords = (const int*)d_in[0];
    const int* sx = (const int*)d_in[1];
    const int* sy = (const int*)d_in[2];
    const int* sz = (const int*)d_in[3];
    (void)n_in;

    int M = in_sizes[0] / 4;                    // number of points
    unsigned total_quads = (unsigned)M * 48u;   // (M*192)/4 float4s

    build_table_kernel<<<(TABLE_ELEMS + 255) / 256, 256>>>(sx, sy, sz);

    // 256 quads per warp, 8 warps per block -> 2048 quads per block
    if (total_quads % 2048u == 0u) {
        int n_blocks = total_quads / 2048u;     // 7680 for the bench shape
        fill_kernel_exact<<<n_blocks, 256>>>(coords, (float4*)d_out);
    } else {
        int n_blocks = (total_quads + 2047u) / 2048u;
        fill_kernel_guarded<<<n_blocks, 256>>>(coords, (float4*)d_out, total_quads);
    }
    (void)out_size;
}